// round 7
// baseline (speedup 1.0000x reference)
#include <cuda_runtime.h>
#include <math.h>

#define N_NODES 8192
#define D 256
#define MAXNNZ 128
#define EXT_BLOCKS 296   // 2 per SM: low occupancy so GEMM co-schedules on top

// Scratch: ELL adjacency (4 matrices) + 8 feature buffers [8192,256] fp32
__device__ int   g_cols[4][N_NODES * MAXNNZ];
__device__ int   g_len[4][N_NODES];
__device__ float g_buf[8][N_NODES * D];

// Side stream + events for overlapping extract with layer-1 GEMMs.
static cudaStream_t g_s2 = nullptr;
static cudaEvent_t  g_evF = nullptr, g_evJ = nullptr;
static int g_sinit = []() {
    if (cudaStreamCreateWithFlags(&g_s2, cudaStreamNonBlocking) != cudaSuccess) { g_s2 = nullptr; return 0; }
    if (cudaEventCreateWithFlags(&g_evF, cudaEventDisableTiming) != cudaSuccess) { g_s2 = nullptr; return 0; }
    if (cudaEventCreateWithFlags(&g_evJ, cudaEventDisableTiming) != cudaSuccess) { g_s2 = nullptr; return 0; }
    return 1;
}();

// ---------------------------------------------------------------------------
// Persistent low-occupancy extract: binary adjacency -> ELL.
// grid = EXT_BLOCKS (2/SM), 8 warps/block, each warp loops over rows.
// Explicit next-chunk prefetch gives MLP>=2 per warp so 2368 warps can
// stream ~1 GB of adjacency while the GEMM owns the rest of the SM.
// ---------------------------------------------------------------------------
__global__ void __launch_bounds__(256) extract_kernel(
    const float* __restrict__ a0, const float* __restrict__ a1,
    const float* __restrict__ a2, const float* __restrict__ a3)
{
    int wid  = threadIdx.x >> 5;
    int lane = threadIdx.x & 31;
    for (int rg = blockIdx.x * 8 + wid; rg < 4 * N_NODES; rg += EXT_BLOCKS * 8) {
        int mat = rg >> 13;
        int row = rg & (N_NODES - 1);
        const float* A = (mat == 0) ? a0 : (mat == 1) ? a1 : (mat == 2) ? a2 : a3;
        const float* arow = A + (size_t)row * N_NODES;
        int* cols = &g_cols[mat][row * MAXNNZ];
        int base = 0;
        float4 cur = *(const float4*)(arow + lane * 4);
        for (int c0 = 0; c0 < N_NODES; c0 += 128) {
            float4 nxt;
            if (c0 + 128 < N_NODES)
                nxt = *(const float4*)(arow + c0 + 128 + lane * 4);
            float vv[4] = {cur.x, cur.y, cur.z, cur.w};
            #pragma unroll
            for (int j = 0; j < 4; j++) {
                bool nz = (vv[j] != 0.0f);
                unsigned m = __ballot_sync(0xffffffffu, nz);
                if (nz) {
                    int off = base + __popc(m & ((1u << lane) - 1u));
                    if (off < MAXNNZ) cols[off] = c0 + lane * 4 + j;
                }
                base += __popc(m);
            }
            cur = nxt;
        }
        if (lane == 0) g_len[mat][row] = base < MAXNNZ ? base : MAXNNZ;
    }
}

// ---------------------------------------------------------------------------
// Fused 6-in-1 tf32 tensor-core GEMM (both node types in one launch).
// mats 0..2 use X0, mats 3..5 use X1. Each: Ci = X @ Wi^T + bi.
// grid = (12, 64). Block tile 128x128, BK=16 double-buffered,
// 8 warps x (32x64) m16n8k8 tf32. Smem stride 20: conflict-free.
// ---------------------------------------------------------------------------
__device__ __forceinline__ unsigned f2tf32(float f) {
    unsigned r;
    asm("cvt.rna.tf32.f32 %0, %1;" : "=r"(r) : "f"(f));
    return r;
}

__device__ __forceinline__ void mma_tf32(float* c, const unsigned* a, const unsigned* b) {
    asm volatile(
        "mma.sync.aligned.m16n8k8.row.col.f32.tf32.tf32.f32 "
        "{%0,%1,%2,%3}, {%4,%5,%6,%7}, {%8,%9}, {%0,%1,%2,%3};"
        : "+f"(c[0]), "+f"(c[1]), "+f"(c[2]), "+f"(c[3])
        : "r"(a[0]), "r"(a[1]), "r"(a[2]), "r"(a[3]), "r"(b[0]), "r"(b[1]));
}

#define SST 20   // smem row stride (floats)

__global__ void __launch_bounds__(256) gemm6_mma(
    const float* __restrict__ X0, const float* __restrict__ X1,
    const float* __restrict__ W0, const float* __restrict__ W1, const float* __restrict__ W2,
    const float* __restrict__ W3, const float* __restrict__ W4, const float* __restrict__ W5,
    const float* __restrict__ b0, const float* __restrict__ b1, const float* __restrict__ b2,
    const float* __restrict__ b3, const float* __restrict__ b4, const float* __restrict__ b5,
    float* __restrict__ C0, float* __restrict__ C1, float* __restrict__ C2,
    float* __restrict__ C3, float* __restrict__ C4, float* __restrict__ C5, int K)
{
    __shared__ float As[2][128 * SST];
    __shared__ float Bs[2][128 * SST];

    int tid  = threadIdx.x;
    int nblk = blockIdx.x;
    int mat  = nblk >> 1;
    int n0   = (nblk & 1) * 128;
    int m0   = blockIdx.y * 128;

    const float* X = (mat < 3) ? X0 : X1;
    const float* W = (mat == 0) ? W0 : (mat == 1) ? W1 : (mat == 2) ? W2 :
                     (mat == 3) ? W3 : (mat == 4) ? W4 : W5;
    const float* bias = (mat == 0) ? b0 : (mat == 1) ? b1 : (mat == 2) ? b2 :
                        (mat == 3) ? b3 : (mat == 4) ? b4 : b5;
    float* C = (mat == 0) ? C0 : (mat == 1) ? C1 : (mat == 2) ? C2 :
               (mat == 3) ? C3 : (mat == 4) ? C4 : C5;

    int wid = tid >> 5, lane = tid & 31;
    int wm = (wid >> 1) * 32;
    int wn = (wid & 1) * 64;
    int gid = lane >> 2;
    int tg  = lane & 3;

    float acc[2][8][4];
    #pragma unroll
    for (int i = 0; i < 2; i++)
        #pragma unroll
        for (int j = 0; j < 8; j++)
            #pragma unroll
            for (int k = 0; k < 4; k++) acc[i][j][k] = 0.0f;

    int lrow = tid >> 2;
    int lc4  = (tid & 3) * 4;

    int nkc = K >> 4;
    float4 xv[2], wv[2];

    #pragma unroll
    for (int i = 0; i < 2; i++) {
        int r = i * 64 + lrow;
        xv[i] = *(const float4*)(X + (size_t)(m0 + r) * K + lc4);
        wv[i] = *(const float4*)(W + (size_t)(n0 + r) * K + lc4);
    }
    #pragma unroll
    for (int i = 0; i < 2; i++) {
        int base = (i * 64 + lrow) * SST + lc4;
        As[0][base + 0] = __uint_as_float(f2tf32(xv[i].x));
        As[0][base + 1] = __uint_as_float(f2tf32(xv[i].y));
        As[0][base + 2] = __uint_as_float(f2tf32(xv[i].z));
        As[0][base + 3] = __uint_as_float(f2tf32(xv[i].w));
        Bs[0][base + 0] = __uint_as_float(f2tf32(wv[i].x));
        Bs[0][base + 1] = __uint_as_float(f2tf32(wv[i].y));
        Bs[0][base + 2] = __uint_as_float(f2tf32(wv[i].z));
        Bs[0][base + 3] = __uint_as_float(f2tf32(wv[i].w));
    }
    __syncthreads();

    for (int kc = 0; kc < nkc; kc++) {
        int buf = kc & 1;
        bool more = (kc + 1) < nkc;
        if (more) {
            int koff = (kc + 1) * 16;
            #pragma unroll
            for (int i = 0; i < 2; i++) {
                int r = i * 64 + lrow;
                xv[i] = *(const float4*)(X + (size_t)(m0 + r) * K + koff + lc4);
                wv[i] = *(const float4*)(W + (size_t)(n0 + r) * K + koff + lc4);
            }
        }
        #pragma unroll
        for (int k8 = 0; k8 < 16; k8 += 8) {
            unsigned a[2][4];
            #pragma unroll
            for (int mt = 0; mt < 2; mt++) {
                int r = wm + mt * 16 + gid;
                a[mt][0] = __float_as_uint(As[buf][(r)     * SST + k8 + tg]);
                a[mt][1] = __float_as_uint(As[buf][(r + 8) * SST + k8 + tg]);
                a[mt][2] = __float_as_uint(As[buf][(r)     * SST + k8 + tg + 4]);
                a[mt][3] = __float_as_uint(As[buf][(r + 8) * SST + k8 + tg + 4]);
            }
            #pragma unroll
            for (int nt = 0; nt < 8; nt++) {
                int rn = wn + nt * 8 + gid;
                unsigned b[2];
                b[0] = __float_as_uint(Bs[buf][rn * SST + k8 + tg]);
                b[1] = __float_as_uint(Bs[buf][rn * SST + k8 + tg + 4]);
                mma_tf32(acc[0][nt], a[0], b);
                mma_tf32(acc[1][nt], a[1], b);
            }
        }
        __syncthreads();
        if (more) {
            int ob = buf ^ 1;
            #pragma unroll
            for (int i = 0; i < 2; i++) {
                int base = (i * 64 + lrow) * SST + lc4;
                As[ob][base + 0] = __uint_as_float(f2tf32(xv[i].x));
                As[ob][base + 1] = __uint_as_float(f2tf32(xv[i].y));
                As[ob][base + 2] = __uint_as_float(f2tf32(xv[i].z));
                As[ob][base + 3] = __uint_as_float(f2tf32(xv[i].w));
                Bs[ob][base + 0] = __uint_as_float(f2tf32(wv[i].x));
                Bs[ob][base + 1] = __uint_as_float(f2tf32(wv[i].y));
                Bs[ob][base + 2] = __uint_as_float(f2tf32(wv[i].z));
                Bs[ob][base + 3] = __uint_as_float(f2tf32(wv[i].w));
            }
            __syncthreads();
        }
    }

    #pragma unroll
    for (int mt = 0; mt < 2; mt++) {
        #pragma unroll
        for (int nt = 0; nt < 8; nt++) {
            int col = n0 + wn + nt * 8 + tg * 2;
            float2 bv = *(const float2*)(bias + col);
            int r0 = m0 + wm + mt * 16 + gid;
            float2 o0 = {acc[mt][nt][0] + bv.x, acc[mt][nt][1] + bv.y};
            float2 o1 = {acc[mt][nt][2] + bv.x, acc[mt][nt][3] + bv.y};
            *(float2*)(C + (size_t)r0 * D + col)       = o0;
            *(float2*)(C + (size_t)(r0 + 8) * D + col) = o1;
        }
    }
}

// ---------------------------------------------------------------------------
// Fused dual combine: blocks [0,2048) config P, [2048,4096) config Q.
// float4, 64 thr/row, 4 rows/block. Optional fused L2 row norm.
// ---------------------------------------------------------------------------
__global__ void __launch_bounds__(256) combine2x_kernel(
    const float* __restrict__ P0, const float* __restrict__ XA0, const float* __restrict__ XB0,
    int mA0, int mB0, float* __restrict__ out0,
    const float* __restrict__ P1, const float* __restrict__ XA1, const float* __restrict__ XB1,
    int mA1, int mB1, float* __restrict__ out1,
    int do_norm)
{
    __shared__ int sA[4][MAXNNZ];
    __shared__ int sB[4][MAXNNZ];
    __shared__ float red[4][2];

    int blk = blockIdx.x;
    const float *P, *XA, *XB;
    float* out;
    int matA, matB, rowbase;
    if (blk < 2048) {
        P = P0; XA = XA0; XB = XB0; out = out0; matA = mA0; matB = mB0;
        rowbase = blk * 4;
    } else {
        P = P1; XA = XA1; XB = XB1; out = out1; matA = mA1; matB = mB1;
        rowbase = (blk - 2048) * 4;
    }

    int tid = threadIdx.x;
    int r   = tid >> 6;
    int t   = tid & 63;
    int row = rowbase + r;

    int lenA = g_len[matA][row];
    int lenB = g_len[matB][row];
    {
        const int* cA = &g_cols[matA][row * MAXNNZ];
        const int* cB = &g_cols[matB][row * MAXNNZ];
        if (t      < lenA) sA[r][t]      = cA[t];
        if (t + 64 < lenA) sA[r][t + 64] = cA[t + 64];
        if (t      < lenB) sB[r][t]      = cB[t];
        if (t + 64 < lenB) sB[r][t + 64] = cB[t + 64];
    }
    __syncthreads();

    int c4 = t * 4;
    float4 acc = *(const float4*)(P + (size_t)row * D + c4);
    #pragma unroll 4
    for (int i = 0; i < lenA; i++) {
        float4 v = *(const float4*)(XA + (size_t)sA[r][i] * D + c4);
        acc.x += v.x; acc.y += v.y; acc.z += v.z; acc.w += v.w;
    }
    #pragma unroll 4
    for (int i = 0; i < lenB; i++) {
        float4 v = *(const float4*)(XB + (size_t)sB[r][i] * D + c4);
        acc.x += v.x; acc.y += v.y; acc.z += v.z; acc.w += v.w;
    }
    acc.x = acc.x > 0.0f ? acc.x : 0.1f * acc.x;
    acc.y = acc.y > 0.0f ? acc.y : 0.1f * acc.y;
    acc.z = acc.z > 0.0f ? acc.z : 0.1f * acc.z;
    acc.w = acc.w > 0.0f ? acc.w : 0.1f * acc.w;

    if (do_norm) {
        float s = acc.x * acc.x + acc.y * acc.y + acc.z * acc.z + acc.w * acc.w;
        #pragma unroll
        for (int off = 16; off > 0; off >>= 1)
            s += __shfl_xor_sync(0xffffffffu, s, off);
        if ((t & 31) == 0) red[r][t >> 5] = s;
        __syncthreads();
        float inv = 1.0f / (sqrtf(red[r][0] + red[r][1]) + 1e-9f);
        acc.x *= inv; acc.y *= inv; acc.z *= inv; acc.w *= inv;
    }
    *(float4*)(out + (size_t)row * D + c4) = acc;
}

// ---------------------------------------------------------------------------
extern "C" void kernel_launch(void* const* d_in, const int* in_sizes, int n_in,
                              void* d_out, int out_size)
{
    const float* hp         = (const float*)d_in[0];
    const float* hq         = (const float*)d_in[1];
    const float* a_cons     = (const float*)d_in[2];
    const float* a_prod     = (const float*)d_in[3];
    const float* a_rev_cons = (const float*)d_in[4];
    const float* a_rev_prod = (const float*)d_in[5];
    const float* w[12];
    const float* b[12];
    for (int i = 0; i < 12; i++) {
        w[i] = (const float*)d_in[6 + 2 * i];
        b[i] = (const float*)d_in[7 + 2 * i];
    }
    float* out = (float*)d_out;

    void* symp = nullptr;
    cudaGetSymbolAddress(&symp, g_buf);
    float* B0 = (float*)symp;
    #define BUF(i) (B0 + (size_t)(i) * N_NODES * D)

    dim3 gg(12, N_NODES / 128), gb(256);

    // Extract (persistent, 2 blocks/SM) on the side stream FIRST, so its
    // 296 blocks occupy a thin slice of every SM; the layer-1 GEMM launched
    // next co-schedules on the remaining resources -> true overlap.
    // mats: 0=a_cons, 1=a_prod, 2=a_rev_cons, 3=a_rev_prod
    bool fork = (g_sinit && g_s2);
    if (fork) {
        cudaEventRecord(g_evF, 0);
        cudaStreamWaitEvent(g_s2, g_evF, 0);
        extract_kernel<<<EXT_BLOCKS, 256, 0, g_s2>>>(a_cons, a_prod, a_rev_cons, a_rev_prod);
        cudaEventRecord(g_evJ, g_s2);
    } else {
        extract_kernel<<<EXT_BLOCKS, 256>>>(a_cons, a_prod, a_rev_cons, a_rev_prod);
    }

    // ---- layer 1 (K = 512) ----
    // P-side (mats 0..2): X=hp -> {wp1->BUF0, wprod1->BUF4, wrcons1->BUF5}
    // Q-side (mats 3..5): X=hq -> {wq1->BUF1, wcons1->BUF2, wrprod1->BUF3}
    gemm6_mma<<<gg, gb>>>(hp, hq,
                          w[0], w[4], w[5], w[1], w[2], w[3],
                          b[0], b[4], b[5], b[1], b[2], b[3],
                          BUF(0), BUF(4), BUF(5), BUF(1), BUF(2), BUF(3), 512);
    if (fork) cudaStreamWaitEvent(0, g_evJ, 0);

    // hp1 = act(BUF0 + a_cons@BUF2 + a_rev_prod@BUF3) ; hq1 analogous
    combine2x_kernel<<<4096, 256>>>(
        BUF(0), BUF(2), BUF(3), 0, 3, BUF(6),
        BUF(1), BUF(4), BUF(5), 1, 2, BUF(7), 0);

    // ---- layer 2 (K = 256) ----
    gemm6_mma<<<gg, gb>>>(BUF(6), BUF(7),
                          w[6], w[10], w[11], w[7], w[8], w[9],
                          b[6], b[10], b[11], b[7], b[8], b[9],
                          BUF(0), BUF(4), BUF(5), BUF(1), BUF(2), BUF(3), 256);

    combine2x_kernel<<<4096, 256>>>(
        BUF(0), BUF(2), BUF(3), 0, 3, out,
        BUF(1), BUF(4), BUF(5), 1, 2, out + (size_t)N_NODES * D, 1);
    #undef BUF
}

// round 9
// speedup vs baseline: 1.4642x; 1.4642x over previous
#include <cuda_runtime.h>
#include <math.h>

#define N_NODES 8192
#define D 256
#define MAXNNZ 128

// Scratch: ELL adjacency (4 matrices) + 8 feature buffers [8192,256] fp32
__device__ int   g_cols[4][N_NODES * MAXNNZ];
__device__ int   g_len[4][N_NODES];
__device__ float g_buf[8][N_NODES * D];

// ---------------------------------------------------------------------------
// Extract binary adjacency -> ELL. One warp per row, ballot compaction.
// Wide grid, serial (overlap attempts R4/R6/R7 all failed or regressed).
// ---------------------------------------------------------------------------
__global__ void extract_kernel(const float* __restrict__ a0,
                               const float* __restrict__ a1,
                               const float* __restrict__ a2,
                               const float* __restrict__ a3)
{
    int gw   = (blockIdx.x * blockDim.x + threadIdx.x) >> 5;
    int lane = threadIdx.x & 31;
    int mat  = gw >> 13;
    int row  = gw & (N_NODES - 1);
    const float* A = (mat == 0) ? a0 : (mat == 1) ? a1 : (mat == 2) ? a2 : a3;
    const float* arow = A + (size_t)row * N_NODES;
    int* cols = &g_cols[mat][row * MAXNNZ];
    int base = 0;
    for (int c0 = 0; c0 < N_NODES; c0 += 128) {
        float4 v = *(const float4*)(arow + c0 + lane * 4);
        float vv[4] = {v.x, v.y, v.z, v.w};
        #pragma unroll
        for (int j = 0; j < 4; j++) {
            bool nz = (vv[j] != 0.0f);
            unsigned m = __ballot_sync(0xffffffffu, nz);
            if (nz) {
                int off = base + __popc(m & ((1u << lane) - 1u));
                if (off < MAXNNZ) cols[off] = c0 + lane * 4 + j;
            }
            base += __popc(m);
        }
    }
    if (lane == 0) g_len[mat][row] = base < MAXNNZ ? base : MAXNNZ;
}

// ---------------------------------------------------------------------------
// cp.async helpers
// ---------------------------------------------------------------------------
__device__ __forceinline__ unsigned smem_u32(const void* p) {
    return (unsigned)__cvta_generic_to_shared(p);
}
__device__ __forceinline__ void cp16(unsigned dst, const float* src) {
    asm volatile("cp.async.cg.shared.global [%0], [%1], 16;" :: "r"(dst), "l"(src));
}
__device__ __forceinline__ void cp_commit() {
    asm volatile("cp.async.commit_group;");
}
template <int N>
__device__ __forceinline__ void cp_wait() {
    asm volatile("cp.async.wait_group %0;" :: "n"(N));
}

__device__ __forceinline__ void mma_tf32(float* c, const unsigned* a, const unsigned* b) {
    asm volatile(
        "mma.sync.aligned.m16n8k8.row.col.f32.tf32.tf32.f32 "
        "{%0,%1,%2,%3}, {%4,%5,%6,%7}, {%8,%9}, {%0,%1,%2,%3};"
        : "+f"(c[0]), "+f"(c[1]), "+f"(c[2]), "+f"(c[3])
        : "r"(a[0]), "r"(a[1]), "r"(a[2]), "r"(a[3]), "r"(b[0]), "r"(b[1]));
}

#define SST 20      // smem row stride in floats (80B = 5x16B: cp.async-aligned, conflict-free)
#define NSTAGE 4    // cp.async ring stages
#define PD 3        // prefetch distance
#define STAGE_FLOATS (128 * SST)                       // 2560 floats per tile stage
#define GEMM_SMEM_BYTES (2 * NSTAGE * STAGE_FLOATS * 4) // 81920 bytes (dynamic)

// ---------------------------------------------------------------------------
// Fused 6-in-1 tf32 tensor-core GEMM, cp.async 4-stage pipeline, dynamic smem.
// mats 0..2 use X0, mats 3..5 use X1. Each: Ci = X @ Wi^T + bi  (Wi [256,K]).
// grid = (12, 64). Block tile 128x128, BK=16, 8 warps x (32x64) m16n8k8.
// fp32 data fed directly to tf32 mma (HW truncates mantissa; no cvt ALU).
// One __syncthreads per K-chunk.
// ---------------------------------------------------------------------------
__global__ void __launch_bounds__(256) gemm6_mma(
    const float* __restrict__ X0, const float* __restrict__ X1,
    const float* __restrict__ W0, const float* __restrict__ W1, const float* __restrict__ W2,
    const float* __restrict__ W3, const float* __restrict__ W4, const float* __restrict__ W5,
    const float* __restrict__ b0, const float* __restrict__ b1, const float* __restrict__ b2,
    const float* __restrict__ b3, const float* __restrict__ b4, const float* __restrict__ b5,
    float* __restrict__ C0, float* __restrict__ C1, float* __restrict__ C2,
    float* __restrict__ C3, float* __restrict__ C4, float* __restrict__ C5, int K)
{
    extern __shared__ float smem[];
    float* Asm = smem;                              // NSTAGE * STAGE_FLOATS
    float* Bsm = smem + NSTAGE * STAGE_FLOATS;      // NSTAGE * STAGE_FLOATS

    int tid  = threadIdx.x;
    int nblk = blockIdx.x;
    int mat  = nblk >> 1;
    int n0   = (nblk & 1) * 128;
    int m0   = blockIdx.y * 128;

    const float* X = (mat < 3) ? X0 : X1;
    const float* W = (mat == 0) ? W0 : (mat == 1) ? W1 : (mat == 2) ? W2 :
                     (mat == 3) ? W3 : (mat == 4) ? W4 : W5;
    const float* bias = (mat == 0) ? b0 : (mat == 1) ? b1 : (mat == 2) ? b2 :
                        (mat == 3) ? b3 : (mat == 4) ? b4 : b5;
    float* C = (mat == 0) ? C0 : (mat == 1) ? C1 : (mat == 2) ? C2 :
               (mat == 3) ? C3 : (mat == 4) ? C4 : C5;

    int wid = tid >> 5, lane = tid & 31;
    int wm = (wid >> 1) * 32;      // warp M offset
    int wn = (wid & 1) * 64;       // warp N offset
    int gid = lane >> 2;           // 0..7
    int tg  = lane & 3;            // 0..3

    int lrow = tid >> 2;           // 0..63
    int lc4  = (tid & 3) * 4;      // 0,4,8,12

    // per-thread global source base pointers (2 rows each for A and B tiles)
    const float* xp0 = X + (size_t)(m0 + lrow)      * K + lc4;
    const float* xp1 = X + (size_t)(m0 + lrow + 64) * K + lc4;
    const float* wp0 = W + (size_t)(n0 + lrow)      * K + lc4;
    const float* wp1 = W + (size_t)(n0 + lrow + 64) * K + lc4;
    // smem dst addresses for stage 0
    unsigned ad0 = smem_u32(&Asm[(lrow)      * SST + lc4]);
    unsigned ad1 = smem_u32(&Asm[(lrow + 64) * SST + lc4]);
    unsigned bd0 = smem_u32(&Bsm[(lrow)      * SST + lc4]);
    unsigned bd1 = smem_u32(&Bsm[(lrow + 64) * SST + lc4]);
    const unsigned STB = STAGE_FLOATS * 4;  // bytes per stage

    float acc[2][8][4];
    #pragma unroll
    for (int i = 0; i < 2; i++)
        #pragma unroll
        for (int j = 0; j < 8; j++)
            #pragma unroll
            for (int k = 0; k < 4; k++) acc[i][j][k] = 0.0f;

    int nkc = K >> 4;

    // prologue: issue first PD stages
    #pragma unroll
    for (int s = 0; s < PD; s++) {
        if (s < nkc) {
            int koff = s * 16;
            unsigned so = s * STB;
            cp16(ad0 + so, xp0 + koff);
            cp16(ad1 + so, xp1 + koff);
            cp16(bd0 + so, wp0 + koff);
            cp16(bd1 + so, wp1 + koff);
            cp_commit();
        }
    }

    for (int kc = 0; kc < nkc; kc++) {
        // barrier: all warps done computing the stage about to be refilled
        __syncthreads();
        if (kc + PD < nkc) {
            int koff = (kc + PD) * 16;
            unsigned so = ((kc + PD) & (NSTAGE - 1)) * STB;
            cp16(ad0 + so, xp0 + koff);
            cp16(ad1 + so, xp1 + koff);
            cp16(bd0 + so, wp0 + koff);
            cp16(bd1 + so, wp1 + koff);
            cp_commit();
        }
        // wait for group kc: leave at most (#groups newer than kc) outstanding
        int rem = nkc - 1 - kc;
        if (rem >= PD)      cp_wait<PD>();
        else if (rem == 2)  cp_wait<2>();
        else if (rem == 1)  cp_wait<1>();
        else                cp_wait<0>();

        const float* Ab = Asm + (kc & (NSTAGE - 1)) * STAGE_FLOATS;
        const float* Bb = Bsm + (kc & (NSTAGE - 1)) * STAGE_FLOATS;
        #pragma unroll
        for (int k8 = 0; k8 < 16; k8 += 8) {
            unsigned a[2][4];
            #pragma unroll
            for (int mt = 0; mt < 2; mt++) {
                int r = wm + mt * 16 + gid;
                a[mt][0] = __float_as_uint(Ab[(r)     * SST + k8 + tg]);
                a[mt][1] = __float_as_uint(Ab[(r + 8) * SST + k8 + tg]);
                a[mt][2] = __float_as_uint(Ab[(r)     * SST + k8 + tg + 4]);
                a[mt][3] = __float_as_uint(Ab[(r + 8) * SST + k8 + tg + 4]);
            }
            #pragma unroll
            for (int nt = 0; nt < 8; nt++) {
                int rn = wn + nt * 8 + gid;
                unsigned b[2];
                b[0] = __float_as_uint(Bb[rn * SST + k8 + tg]);
                b[1] = __float_as_uint(Bb[rn * SST + k8 + tg + 4]);
                mma_tf32(acc[0][nt], a[0], b);
                mma_tf32(acc[1][nt], a[1], b);
            }
        }
    }

    // epilogue: add bias, store
    #pragma unroll
    for (int mt = 0; mt < 2; mt++) {
        #pragma unroll
        for (int nt = 0; nt < 8; nt++) {
            int col = n0 + wn + nt * 8 + tg * 2;
            float2 bv = *(const float2*)(bias + col);
            int r0 = m0 + wm + mt * 16 + gid;
            float2 o0 = {acc[mt][nt][0] + bv.x, acc[mt][nt][1] + bv.y};
            float2 o1 = {acc[mt][nt][2] + bv.x, acc[mt][nt][3] + bv.y};
            *(float2*)(C + (size_t)r0 * D + col)       = o0;
            *(float2*)(C + (size_t)(r0 + 8) * D + col) = o1;
        }
    }
}

// ---------------------------------------------------------------------------
// Fused dual combine: blocks [0,2048) config P, [2048,4096) config Q.
// float4, 64 thr/row, 4 rows/block. Optional fused L2 row norm.
// ---------------------------------------------------------------------------
__global__ void __launch_bounds__(256) combine2x_kernel(
    const float* __restrict__ P0, const float* __restrict__ XA0, const float* __restrict__ XB0,
    int mA0, int mB0, float* __restrict__ out0,
    const float* __restrict__ P1, const float* __restrict__ XA1, const float* __restrict__ XB1,
    int mA1, int mB1, float* __restrict__ out1,
    int do_norm)
{
    __shared__ int sA[4][MAXNNZ];
    __shared__ int sB[4][MAXNNZ];
    __shared__ float red[4][2];

    int blk = blockIdx.x;
    const float *P, *XA, *XB;
    float* out;
    int matA, matB, rowbase;
    if (blk < 2048) {
        P = P0; XA = XA0; XB = XB0; out = out0; matA = mA0; matB = mB0;
        rowbase = blk * 4;
    } else {
        P = P1; XA = XA1; XB = XB1; out = out1; matA = mA1; matB = mB1;
        rowbase = (blk - 2048) * 4;
    }

    int tid = threadIdx.x;
    int r   = tid >> 6;
    int t   = tid & 63;
    int row = rowbase + r;

    int lenA = g_len[matA][row];
    int lenB = g_len[matB][row];
    {
        const int* cA = &g_cols[matA][row * MAXNNZ];
        const int* cB = &g_cols[matB][row * MAXNNZ];
        if (t      < lenA) sA[r][t]      = cA[t];
        if (t + 64 < lenA) sA[r][t + 64] = cA[t + 64];
        if (t      < lenB) sB[r][t]      = cB[t];
        if (t + 64 < lenB) sB[r][t + 64] = cB[t + 64];
    }
    __syncthreads();

    int c4 = t * 4;
    float4 acc = *(const float4*)(P + (size_t)row * D + c4);
    #pragma unroll 4
    for (int i = 0; i < lenA; i++) {
        float4 v = *(const float4*)(XA + (size_t)sA[r][i] * D + c4);
        acc.x += v.x; acc.y += v.y; acc.z += v.z; acc.w += v.w;
    }
    #pragma unroll 4
    for (int i = 0; i < lenB; i++) {
        float4 v = *(const float4*)(XB + (size_t)sB[r][i] * D + c4);
        acc.x += v.x; acc.y += v.y; acc.z += v.z; acc.w += v.w;
    }
    acc.x = acc.x > 0.0f ? acc.x : 0.1f * acc.x;
    acc.y = acc.y > 0.0f ? acc.y : 0.1f * acc.y;
    acc.z = acc.z > 0.0f ? acc.z : 0.1f * acc.z;
    acc.w = acc.w > 0.0f ? acc.w : 0.1f * acc.w;

    if (do_norm) {
        float s = acc.x * acc.x + acc.y * acc.y + acc.z * acc.z + acc.w * acc.w;
        #pragma unroll
        for (int off = 16; off > 0; off >>= 1)
            s += __shfl_xor_sync(0xffffffffu, s, off);
        if ((t & 31) == 0) red[r][t >> 5] = s;
        __syncthreads();
        float inv = 1.0f / (sqrtf(red[r][0] + red[r][1]) + 1e-9f);
        acc.x *= inv; acc.y *= inv; acc.z *= inv; acc.w *= inv;
    }
    *(float4*)(out + (size_t)row * D + c4) = acc;
}

// ---------------------------------------------------------------------------
extern "C" void kernel_launch(void* const* d_in, const int* in_sizes, int n_in,
                              void* d_out, int out_size)
{
    const float* hp         = (const float*)d_in[0];
    const float* hq         = (const float*)d_in[1];
    const float* a_cons     = (const float*)d_in[2];
    const float* a_prod     = (const float*)d_in[3];
    const float* a_rev_cons = (const float*)d_in[4];
    const float* a_rev_prod = (const float*)d_in[5];
    const float* w[12];
    const float* b[12];
    for (int i = 0; i < 12; i++) {
        w[i] = (const float*)d_in[6 + 2 * i];
        b[i] = (const float*)d_in[7 + 2 * i];
    }
    float* out = (float*)d_out;

    // Opt in to >48KB dynamic smem for the GEMM (idempotent; not a stream op,
    // no allocation — safe under graph capture).
    cudaFuncSetAttribute(gemm6_mma, cudaFuncAttributeMaxDynamicSharedMemorySize,
                         GEMM_SMEM_BYTES);

    void* symp = nullptr;
    cudaGetSymbolAddress(&symp, g_buf);
    float* B0 = (float*)symp;
    #define BUF(i) (B0 + (size_t)(i) * N_NODES * D)

    // adjacency ELL: 0=a_cons, 1=a_prod, 2=a_rev_cons, 3=a_rev_prod
    extract_kernel<<<4 * N_NODES / 8, 256>>>(a_cons, a_prod, a_rev_cons, a_rev_prod);

    dim3 gg(12, N_NODES / 128), gb(256);
    // ---- layer 1 (K = 512) ----
    // P-side (mats 0..2): X=hp -> {wp1->BUF0, wprod1->BUF4, wrcons1->BUF5}
    // Q-side (mats 3..5): X=hq -> {wq1->BUF1, wcons1->BUF2, wrprod1->BUF3}
    gemm6_mma<<<gg, gb, GEMM_SMEM_BYTES>>>(hp, hq,
                          w[0], w[4], w[5], w[1], w[2], w[3],
                          b[0], b[4], b[5], b[1], b[2], b[3],
                          BUF(0), BUF(4), BUF(5), BUF(1), BUF(2), BUF(3), 512);
    combine2x_kernel<<<4096, 256>>>(
        BUF(0), BUF(2), BUF(3), 0, 3, BUF(6),
        BUF(1), BUF(4), BUF(5), 1, 2, BUF(7), 0);

    // ---- layer 2 (K = 256) ----
    gemm6_mma<<<gg, gb, GEMM_SMEM_BYTES>>>(BUF(6), BUF(7),
                          w[6], w[10], w[11], w[7], w[8], w[9],
                          b[6], b[10], b[11], b[7], b[8], b[9],
                          BUF(0), BUF(4), BUF(5), BUF(1), BUF(2), BUF(3), 256);
    combine2x_kernel<<<4096, 256>>>(
        BUF(0), BUF(2), BUF(3), 0, 3, out,
        BUF(1), BUF(4), BUF(5), 1, 2, out + (size_t)N_NODES * D, 1);
    #undef BUF
}